// round 9
// baseline (speedup 1.0000x reference)
#include <cuda_runtime.h>
#include <cstdint>

#define T_STEPS 4096
#define BATCH   64
#define NH      128
#define NROWS   (BATCH * T_STEPS)   // 262144
#define NSEG    4
#define SEGT    1024                // steps per segment
#define SCAN_SMEM (216 * 1024)      // blocks GEMM CTA co-residency on scan SMs

// Scratch (allocation-free rule: __device__ globals).
__device__ float g_xp[((size_t)NROWS + 8) * NH];   // padded for scan LDG ring
__device__ float g_h [(size_t)NROWS * NH];
__device__ float g_hstate[BATCH * NH];
__device__ float g_w1t[NH * NH];    // W1x^T : [k][j]
__device__ float g_w2t[NH * NH];    // W2^T  : [k][j]

// ---------------------------------------------------------------------------
// Helpers
// ---------------------------------------------------------------------------
__device__ __forceinline__ uint64_t ffma2(uint64_t a, uint64_t b, uint64_t c) {
    uint64_t d;
    asm("fma.rn.f32x2 %0, %1, %2, %3;" : "=l"(d) : "l"(a), "l"(b), "l"(c));
    return d;
}
__device__ __forceinline__ uint64_t addf2(uint64_t a, uint64_t b) {
    uint64_t d;
    asm("add.rn.f32x2 %0, %1, %2;" : "=l"(d) : "l"(a), "l"(b));
    return d;
}
__device__ __forceinline__ float f2sum(uint64_t v) {
    float lo = __uint_as_float((uint32_t)v);
    float hi = __uint_as_float((uint32_t)(v >> 32));
    return lo + hi;
}
__device__ __forceinline__ uint64_t packf2(float x) {
    uint64_t d;
    asm("mov.b64 %0, {%1, %1};" : "=l"(d) : "f"(x));
    return d;
}
__device__ __forceinline__ void cp_async16(uint32_t saddr, const void* g) {
    asm volatile("cp.async.cg.shared.global [%0], [%1], 16;" :: "r"(saddr), "l"(g));
}
__device__ __forceinline__ void cp_commit() { asm volatile("cp.async.commit_group;"); }
__device__ __forceinline__ void cp_wait1()  { asm volatile("cp.async.wait_group 1;" ::: "memory"); }
#define BARSYNC(id) asm volatile("bar.sync %0, 128;" :: "r"(id) : "memory")

// ---------------------------------------------------------------------------
// Setup: W transposes.  Wt1[k][j] = W1[j][128+k],  Wt2[k][j] = W2[j][k]
// ---------------------------------------------------------------------------
__global__ void transpose_w_kernel(const float* __restrict__ W1,
                                   const float* __restrict__ W2)
{
    const int j = threadIdx.x;        // 128
    const int k = blockIdx.x;         // 128
    g_w1t[k * NH + j] = W1[j * 256 + NH + k];
    g_w2t[k * NH + j] = W2[j * NH + k];
}

// ---------------------------------------------------------------------------
// Tiled SGEMM: out[row, j] = (relu?)( sum_k A[row,k] * Wt[k,j] + bias[j] )
// CTA: 128 rows x 128 cols, 256 threads (16x16), 8x8 tile per thread.
// K = 128 in 8 panels of 16, double-buffered cp.async.
// ---------------------------------------------------------------------------
#define GR 128          // rows per CTA
#define GK 16           // k-panel depth
#define ASTRIDE 20      // padded floats per As row

template<bool RELU>
__global__ void __launch_bounds__(256, 2) gemm_tiled_kernel(
    const float* __restrict__ A, const float* __restrict__ Wt,
    const float* __restrict__ bias, float* __restrict__ out,
    int t_off, int nchunk)
{
    __shared__ __align__(16) float As[2][GR][ASTRIDE];  // 20 KB
    __shared__ __align__(16) float Bs[2][GK][NH];       // 16 KB

    const int tid = threadIdx.x;
    const int tx = tid & 15;
    const int ty = tid >> 4;
    const int b  = blockIdx.x / nchunk;
    const int ch = blockIdx.x % nchunk;
    const size_t base = (size_t)b * T_STEPS + (size_t)t_off + (size_t)ch * GR;
    const float* Ag = A + base * NH;

    const uint32_t sA = (uint32_t)__cvta_generic_to_shared(&As[0][0][0]);
    const uint32_t sB = (uint32_t)__cvta_generic_to_shared(&Bs[0][0][0]);

    auto load_panel = [&](int p, int buf) {
#pragma unroll
        for (int q = 0; q < 2; q++) {
            int idx = tid * 2 + q;
            int row = idx >> 2, sub = idx & 3;
            cp_async16(sA + (uint32_t)(buf * GR * ASTRIDE + row * ASTRIDE + sub * 4) * 4,
                       Ag + (size_t)row * NH + p * GK + sub * 4);
        }
#pragma unroll
        for (int q = 0; q < 2; q++) {
            int idx = tid * 2 + q;
            int kk = idx >> 5, sub = idx & 31;
            cp_async16(sB + (uint32_t)(buf * GK * NH + kk * NH + sub * 4) * 4,
                       Wt + (size_t)(p * GK + kk) * NH + sub * 4);
        }
    };

    uint64_t acc[8][4];
#pragma unroll
    for (int r = 0; r < 8; r++)
#pragma unroll
        for (int c = 0; c < 4; c++) acc[r][c] = 0;

    load_panel(0, 0);
    cp_commit();

#pragma unroll
    for (int p = 0; p < 8; p++) {
        if (p < 7) load_panel(p + 1, (p + 1) & 1);
        cp_commit();
        cp_wait1();
        __syncthreads();

        const int buf = p & 1;
#pragma unroll
        for (int kk = 0; kk < GK; kk++) {
            const float* brow = &Bs[buf][kk][tx * 8];
            ulonglong2 bp0 = *reinterpret_cast<const ulonglong2*>(brow);
            ulonglong2 bp1 = *reinterpret_cast<const ulonglong2*>(brow + 4);
#pragma unroll
            for (int r = 0; r < 8; r++) {
                uint64_t ap = packf2(As[buf][ty * 8 + r][kk]);
                acc[r][0] = ffma2(ap, bp0.x, acc[r][0]);
                acc[r][1] = ffma2(ap, bp0.y, acc[r][1]);
                acc[r][2] = ffma2(ap, bp1.x, acc[r][2]);
                acc[r][3] = ffma2(ap, bp1.y, acc[r][3]);
            }
        }
        __syncthreads();
    }

    float4 bv0 = *reinterpret_cast<const float4*>(&bias[tx * 8]);
    float4 bv1 = *reinterpret_cast<const float4*>(&bias[tx * 8 + 4]);
#pragma unroll
    for (int r = 0; r < 8; r++) {
        float2 c0 = *reinterpret_cast<float2*>(&acc[r][0]);
        float2 c1 = *reinterpret_cast<float2*>(&acc[r][1]);
        float2 c2 = *reinterpret_cast<float2*>(&acc[r][2]);
        float2 c3 = *reinterpret_cast<float2*>(&acc[r][3]);
        float4 o0 = make_float4(c0.x + bv0.x, c0.y + bv0.y, c1.x + bv0.z, c1.y + bv0.w);
        float4 o1 = make_float4(c2.x + bv1.x, c2.y + bv1.y, c3.x + bv1.z, c3.y + bv1.w);
        if (RELU) {
            o0.x = fmaxf(o0.x, 0.f); o0.y = fmaxf(o0.y, 0.f);
            o0.z = fmaxf(o0.z, 0.f); o0.w = fmaxf(o0.w, 0.f);
            o1.x = fmaxf(o1.x, 0.f); o1.y = fmaxf(o1.y, 0.f);
            o1.z = fmaxf(o1.z, 0.f); o1.w = fmaxf(o1.w, 0.f);
        }
        float* op = out + (base + ty * 8 + r) * NH + tx * 8;
        *reinterpret_cast<float4*>(op)     = o0;
        *reinterpret_cast<float4*>(op + 4) = o1;
    }
}

// ---------------------------------------------------------------------------
// Scan segment: SEGT steps of h_t = relu(W1h @ h_{t-1} + xp_t).
// TWO independent chains per block (256 threads): chain = tid>>7, j = tid&127.
// Each chain = 4 warps -> each SMSP holds one warp of EACH chain, so one
// chain's FMAs issue inside the other's barrier/LDS/tail bubbles.
// Chains sync independently via named barriers (ids 1 and 2).
// Thread j of a chain owns W1h row j in regs (64 x f32x2); 4 accumulators.
// xp via 8-deep LDG register ring (g_xp padded; no bounds branch).
// ---------------------------------------------------------------------------
__global__ void __launch_bounds__(256, 1) rnn_scan_kernel(
    const float* __restrict__ W1, float* __restrict__ hseq, int seg)
{
    extern __shared__ __align__(16) float dyn[];   // [2 chains][2][NH]
    const int tid   = threadIdx.x;
    const int chain = tid >> 7;
    const int j     = tid & 127;
    const int b     = blockIdx.x * 2 + chain;
    float (*hbuf)[NH] = reinterpret_cast<float (*)[NH]>(dyn) + chain * 2;

    const size_t row0 = (size_t)b * T_STEPS + (size_t)seg * SEGT;
    const float* xp = g_xp + row0 * NH;
    float*       hs = hseq + row0 * NH;

    uint64_t w[64];
#pragma unroll
    for (int k = 0; k < 64; k++)
        w[k] = *reinterpret_cast<const uint64_t*>(&W1[(size_t)j * 256 + 2 * k]);  // W1h

    hbuf[0][j] = (seg == 0) ? 0.0f : g_hstate[b * NH + j];

    float xr[8];
#pragma unroll
    for (int u = 0; u < 8; u++)
        xr[u] = xp[(size_t)u * NH + j];

    const int barid = 1 + chain;

    for (int t0 = 0; t0 < SEGT; t0 += 8) {
#pragma unroll
        for (int u = 0; u < 8; u++) {
            const int t = t0 + u;
            BARSYNC(barid);                  // own chain only: h_t visible, WAR safe
            const float* hp = hbuf[u & 1];   // t&1 == u&1
            uint64_t a0 = 0, a1 = 0, a2 = 0, a3 = 0;
#pragma unroll
            for (int k = 0; k < 16; k++) {
                ulonglong2 h0 = *reinterpret_cast<const ulonglong2*>(&hp[8 * k]);
                ulonglong2 h1 = *reinterpret_cast<const ulonglong2*>(&hp[8 * k + 4]);
                a0 = ffma2(w[4 * k],     h0.x, a0);
                a1 = ffma2(w[4 * k + 1], h0.y, a1);
                a2 = ffma2(w[4 * k + 2], h1.x, a2);
                a3 = ffma2(w[4 * k + 3], h1.y, a3);
            }
            float s = f2sum(addf2(addf2(a0, a1), addf2(a2, a3))) + xr[u];
            s = fmaxf(s, 0.0f);
            hbuf[(u + 1) & 1][j] = s;        // next step's input (SMEM)
            hs[(size_t)t * NH + j] = s;      // for output projection
            xr[u] = xp[(size_t)(t + 8) * NH + j];   // refill ring (padded)
        }
    }
    BARSYNC(barid);
    g_hstate[b * NH + j] = hbuf[0][j];       // SEGT even -> state in buf 0
}

// ---------------------------------------------------------------------------
// Launch: 4-segment software pipeline.
//   g1s0 -> [scan0 || g1s1,g1s2,g1s3(sB)] -> [scan1 || g2s0(sC)] -> ... -> g2s3
// Scan CTAs (216KB smem) claim their 32 SMs; GEMM CTAs (37KB) cannot
// co-reside there. Scans enqueued before the GEMMs that overlap them.
// ---------------------------------------------------------------------------
extern "C" void kernel_launch(void* const* d_in, const int* in_sizes, int n_in,
                              void* d_out, int out_size)
{
    const float* input = (const float*)d_in[0];   // (64, 4096, 128)
    const float* W1    = (const float*)d_in[1];   // (128, 256)
    const float* b1    = (const float*)d_in[2];   // (128,)
    const float* W2    = (const float*)d_in[3];   // (128, 128)
    const float* b2    = (const float*)d_in[4];   // (128,)
    float* out = (float*)d_out;

    float *xp_ptr, *h_ptr, *w1t_ptr, *w2t_ptr;
    cudaGetSymbolAddress((void**)&xp_ptr,  g_xp);
    cudaGetSymbolAddress((void**)&h_ptr,   g_h);
    cudaGetSymbolAddress((void**)&w1t_ptr, g_w1t);
    cudaGetSymbolAddress((void**)&w2t_ptr, g_w2t);

    cudaFuncSetAttribute(rnn_scan_kernel,
                         cudaFuncAttributeMaxDynamicSharedMemorySize, SCAN_SMEM);

    static cudaStream_t sB = nullptr, sC = nullptr;
    static cudaEvent_t eFork, eC, e1[NSEG], es[NSEG];
    if (sB == nullptr) {
        cudaStreamCreateWithFlags(&sB, cudaStreamNonBlocking);
        cudaStreamCreateWithFlags(&sC, cudaStreamNonBlocking);
        cudaEventCreateWithFlags(&eFork, cudaEventDisableTiming);
        cudaEventCreateWithFlags(&eC,    cudaEventDisableTiming);
        for (int i = 0; i < NSEG; i++) {
            cudaEventCreateWithFlags(&e1[i], cudaEventDisableTiming);
            cudaEventCreateWithFlags(&es[i], cudaEventDisableTiming);
        }
    }

    const int nchunk = SEGT / GR;            // 8 -> grid 512 per segment
    const int grid_seg = BATCH * nchunk;

    // setup + g1s0 (full chip)
    transpose_w_kernel<<<NH, NH>>>(W1, W2);
    gemm_tiled_kernel<false><<<grid_seg, 256>>>(input, w1t_ptr, b1, xp_ptr, 0, nchunk);
    cudaEventRecord(eFork, 0);

    // scan seg 0 enqueued before the side-stream GEMMs (claims its SMs first)
    rnn_scan_kernel<<<BATCH / 2, 256, SCAN_SMEM>>>(W1, h_ptr, 0);
    cudaEventRecord(es[0], 0);

    // remaining xp segments on sB (overlap scan0+)
    cudaStreamWaitEvent(sB, eFork, 0);
    for (int s = 1; s < NSEG; s++) {
        gemm_tiled_kernel<false><<<grid_seg, 256, 0, sB>>>(input, w1t_ptr, b1, xp_ptr, s * SEGT, nchunk);
        cudaEventRecord(e1[s], sB);
    }

    // scans 1..3, each overlapped by the previous segment's output GEMM on sC
    for (int s = 1; s < NSEG; s++) {
        cudaStreamWaitEvent(0, e1[s], 0);
        rnn_scan_kernel<<<BATCH / 2, 256, SCAN_SMEM>>>(W1, h_ptr, s);
        cudaEventRecord(es[s], 0);

        cudaStreamWaitEvent(sC, es[s - 1], 0);
        gemm_tiled_kernel<true><<<grid_seg, 256, 0, sC>>>(h_ptr, w2t_ptr, b2, out, (s - 1) * SEGT, nchunk);
    }
    cudaEventRecord(eC, sC);

    // final output segment on default stream (after scan3)
    gemm_tiled_kernel<true><<<grid_seg, 256>>>(h_ptr, w2t_ptr, b2, out, (NSEG - 1) * SEGT, nchunk);

    // join
    cudaStreamWaitEvent(0, eC, 0);
}

// round 10
// speedup vs baseline: 1.5090x; 1.5090x over previous
#include <cuda_runtime.h>
#include <cstdint>

#define T_STEPS 4096
#define BATCH   64
#define NH      128
#define NROWS   (BATCH * T_STEPS)   // 262144
#define NSEG    8
#define SEGT    512                 // steps per segment (even)
#define SCAN_SMEM (216 * 1024)      // blocks GEMM CTA co-residency on scan SMs

// Scratch (allocation-free rule: __device__ globals).
__device__ float g_xp[((size_t)NROWS + 8) * NH];   // padded for scan LDG ring
__device__ float g_h [(size_t)NROWS * NH];
__device__ float g_hstate[BATCH * NH];
__device__ float g_w1t[NH * NH];    // W1x^T : [k][j]
__device__ float g_w2t[NH * NH];    // W2^T  : [k][j]

// ---------------------------------------------------------------------------
// Helpers
// ---------------------------------------------------------------------------
__device__ __forceinline__ uint64_t ffma2(uint64_t a, uint64_t b, uint64_t c) {
    uint64_t d;
    asm("fma.rn.f32x2 %0, %1, %2, %3;" : "=l"(d) : "l"(a), "l"(b), "l"(c));
    return d;
}
__device__ __forceinline__ uint64_t addf2(uint64_t a, uint64_t b) {
    uint64_t d;
    asm("add.rn.f32x2 %0, %1, %2;" : "=l"(d) : "l"(a), "l"(b));
    return d;
}
__device__ __forceinline__ float f2sum(uint64_t v) {
    float lo = __uint_as_float((uint32_t)v);
    float hi = __uint_as_float((uint32_t)(v >> 32));
    return lo + hi;
}
__device__ __forceinline__ uint64_t packf2(float x) {
    uint64_t d;
    asm("mov.b64 %0, {%1, %1};" : "=l"(d) : "f"(x));
    return d;
}
__device__ __forceinline__ void cp_async16(uint32_t saddr, const void* g) {
    asm volatile("cp.async.cg.shared.global [%0], [%1], 16;" :: "r"(saddr), "l"(g));
}
__device__ __forceinline__ void cp_commit() { asm volatile("cp.async.commit_group;"); }
__device__ __forceinline__ void cp_wait1()  { asm volatile("cp.async.wait_group 1;" ::: "memory"); }

// ---------------------------------------------------------------------------
// Setup: W transposes.  Wt1[k][j] = W1[j][128+k],  Wt2[k][j] = W2[j][k]
// ---------------------------------------------------------------------------
__global__ void transpose_w_kernel(const float* __restrict__ W1,
                                   const float* __restrict__ W2)
{
    const int j = threadIdx.x;        // 128
    const int k = blockIdx.x;         // 128
    g_w1t[k * NH + j] = W1[j * 256 + NH + k];
    g_w2t[k * NH + j] = W2[j * NH + k];
}

// ---------------------------------------------------------------------------
// Tiled SGEMM: out[row, j] = (relu?)( sum_k A[row,k] * Wt[k,j] + bias[j] )
// CTA: 128 rows x 128 cols, 256 threads (16x16), 8x8 tile per thread.
// K = 128 in 8 panels of 16, double-buffered cp.async.
// ---------------------------------------------------------------------------
#define GR 128          // rows per CTA
#define GK 16           // k-panel depth
#define ASTRIDE 20      // padded floats per As row

template<bool RELU>
__global__ void __launch_bounds__(256, 2) gemm_tiled_kernel(
    const float* __restrict__ A, const float* __restrict__ Wt,
    const float* __restrict__ bias, float* __restrict__ out,
    int t_off, int nchunk)
{
    __shared__ __align__(16) float As[2][GR][ASTRIDE];  // 20 KB
    __shared__ __align__(16) float Bs[2][GK][NH];       // 16 KB

    const int tid = threadIdx.x;
    const int tx = tid & 15;
    const int ty = tid >> 4;
    const int b  = blockIdx.x / nchunk;
    const int ch = blockIdx.x % nchunk;
    const size_t base = (size_t)b * T_STEPS + (size_t)t_off + (size_t)ch * GR;
    const float* Ag = A + base * NH;

    const uint32_t sA = (uint32_t)__cvta_generic_to_shared(&As[0][0][0]);
    const uint32_t sB = (uint32_t)__cvta_generic_to_shared(&Bs[0][0][0]);

    auto load_panel = [&](int p, int buf) {
#pragma unroll
        for (int q = 0; q < 2; q++) {
            int idx = tid * 2 + q;
            int row = idx >> 2, sub = idx & 3;
            cp_async16(sA + (uint32_t)(buf * GR * ASTRIDE + row * ASTRIDE + sub * 4) * 4,
                       Ag + (size_t)row * NH + p * GK + sub * 4);
        }
#pragma unroll
        for (int q = 0; q < 2; q++) {
            int idx = tid * 2 + q;
            int kk = idx >> 5, sub = idx & 31;
            cp_async16(sB + (uint32_t)(buf * GK * NH + kk * NH + sub * 4) * 4,
                       Wt + (size_t)(p * GK + kk) * NH + sub * 4);
        }
    };

    uint64_t acc[8][4];
#pragma unroll
    for (int r = 0; r < 8; r++)
#pragma unroll
        for (int c = 0; c < 4; c++) acc[r][c] = 0;

    load_panel(0, 0);
    cp_commit();

#pragma unroll
    for (int p = 0; p < 8; p++) {
        if (p < 7) load_panel(p + 1, (p + 1) & 1);
        cp_commit();
        cp_wait1();
        __syncthreads();

        const int buf = p & 1;
#pragma unroll
        for (int kk = 0; kk < GK; kk++) {
            const float* brow = &Bs[buf][kk][tx * 8];
            ulonglong2 bp0 = *reinterpret_cast<const ulonglong2*>(brow);
            ulonglong2 bp1 = *reinterpret_cast<const ulonglong2*>(brow + 4);
#pragma unroll
            for (int r = 0; r < 8; r++) {
                uint64_t ap = packf2(As[buf][ty * 8 + r][kk]);
                acc[r][0] = ffma2(ap, bp0.x, acc[r][0]);
                acc[r][1] = ffma2(ap, bp0.y, acc[r][1]);
                acc[r][2] = ffma2(ap, bp1.x, acc[r][2]);
                acc[r][3] = ffma2(ap, bp1.y, acc[r][3]);
            }
        }
        __syncthreads();
    }

    float4 bv0 = *reinterpret_cast<const float4*>(&bias[tx * 8]);
    float4 bv1 = *reinterpret_cast<const float4*>(&bias[tx * 8 + 4]);
#pragma unroll
    for (int r = 0; r < 8; r++) {
        float2 c0 = *reinterpret_cast<float2*>(&acc[r][0]);
        float2 c1 = *reinterpret_cast<float2*>(&acc[r][1]);
        float2 c2 = *reinterpret_cast<float2*>(&acc[r][2]);
        float2 c3 = *reinterpret_cast<float2*>(&acc[r][3]);
        float4 o0 = make_float4(c0.x + bv0.x, c0.y + bv0.y, c1.x + bv0.z, c1.y + bv0.w);
        float4 o1 = make_float4(c2.x + bv1.x, c2.y + bv1.y, c3.x + bv1.z, c3.y + bv1.w);
        if (RELU) {
            o0.x = fmaxf(o0.x, 0.f); o0.y = fmaxf(o0.y, 0.f);
            o0.z = fmaxf(o0.z, 0.f); o0.w = fmaxf(o0.w, 0.f);
            o1.x = fmaxf(o1.x, 0.f); o1.y = fmaxf(o1.y, 0.f);
            o1.z = fmaxf(o1.z, 0.f); o1.w = fmaxf(o1.w, 0.f);
        }
        float* op = out + (base + ty * 8 + r) * NH + tx * 8;
        *reinterpret_cast<float4*>(op)     = o0;
        *reinterpret_cast<float4*>(op + 4) = o1;
    }
}

// ---------------------------------------------------------------------------
// Scan segment: SEGT steps of h_t = relu(W1h @ h_{t-1} + xp_t).
// 64 blocks (one chain per SM), 128 threads. Thread j owns W1h row j in regs
// (64 x f32x2). Simple 4-accumulator inner loop (best measured: ~400 cyc/step;
// manual register pipelining was SLOWER due to spills). h double-buffered in
// huge dynamic smem (forces SM exclusivity). xp via 8-deep LDG register ring.
// ---------------------------------------------------------------------------
__global__ void __launch_bounds__(128, 1) rnn_scan_kernel(
    const float* __restrict__ W1, float* __restrict__ hseq, int seg)
{
    extern __shared__ __align__(16) float dyn[];
    float (*hbuf)[NH] = reinterpret_cast<float (*)[NH]>(dyn);

    const int j = threadIdx.x;
    const int b = blockIdx.x;

    const size_t row0 = (size_t)b * T_STEPS + (size_t)seg * SEGT;
    const float* xp = g_xp + row0 * NH;
    float*       hs = hseq + row0 * NH;

    uint64_t w[64];
#pragma unroll
    for (int k = 0; k < 64; k++)
        w[k] = *reinterpret_cast<const uint64_t*>(&W1[(size_t)j * 256 + 2 * k]);  // W1h

    hbuf[0][j] = (seg == 0) ? 0.0f : g_hstate[b * NH + j];

    float xr[8];
#pragma unroll
    for (int u = 0; u < 8; u++)
        xr[u] = xp[(size_t)u * NH + j];

    for (int t0 = 0; t0 < SEGT; t0 += 8) {
#pragma unroll
        for (int u = 0; u < 8; u++) {
            const int t = t0 + u;
            __syncthreads();                 // h_t visible; WAR safe
            const float* hp = hbuf[u & 1];   // t&1 == u&1
            uint64_t a0 = 0, a1 = 0, a2 = 0, a3 = 0;
#pragma unroll
            for (int k = 0; k < 16; k++) {
                ulonglong2 h0 = *reinterpret_cast<const ulonglong2*>(&hp[8 * k]);
                ulonglong2 h1 = *reinterpret_cast<const ulonglong2*>(&hp[8 * k + 4]);
                a0 = ffma2(w[4 * k],     h0.x, a0);
                a1 = ffma2(w[4 * k + 1], h0.y, a1);
                a2 = ffma2(w[4 * k + 2], h1.x, a2);
                a3 = ffma2(w[4 * k + 3], h1.y, a3);
            }
            float s = f2sum(addf2(addf2(a0, a1), addf2(a2, a3))) + xr[u];
            s = fmaxf(s, 0.0f);
            hbuf[(u + 1) & 1][j] = s;        // next step's input (SMEM)
            hs[(size_t)t * NH + j] = s;      // for output projection
            xr[u] = xp[(size_t)(t + 8) * NH + j];   // refill ring (padded)
        }
    }
    __syncthreads();
    g_hstate[b * NH + j] = hbuf[0][j];       // SEGT even -> state in buf 0
}

// ---------------------------------------------------------------------------
// Launch: 8-segment software pipeline.
//   g1s0 -> [scan0 || g1s1..7(sB)] -> [scan s || g2s(s-1)(sC)] ... -> g2s7
// Scan CTAs (216KB smem) claim their 64 SMs first (enqueued before the GEMMs
// that overlap them); GEMM CTAs (37KB) cannot co-reside there.
// ---------------------------------------------------------------------------
extern "C" void kernel_launch(void* const* d_in, const int* in_sizes, int n_in,
                              void* d_out, int out_size)
{
    const float* input = (const float*)d_in[0];   // (64, 4096, 128)
    const float* W1    = (const float*)d_in[1];   // (128, 256)
    const float* b1    = (const float*)d_in[2];   // (128,)
    const float* W2    = (const float*)d_in[3];   // (128, 128)
    const float* b2    = (const float*)d_in[4];   // (128,)
    float* out = (float*)d_out;

    float *xp_ptr, *h_ptr, *w1t_ptr, *w2t_ptr;
    cudaGetSymbolAddress((void**)&xp_ptr,  g_xp);
    cudaGetSymbolAddress((void**)&h_ptr,   g_h);
    cudaGetSymbolAddress((void**)&w1t_ptr, g_w1t);
    cudaGetSymbolAddress((void**)&w2t_ptr, g_w2t);

    cudaFuncSetAttribute(rnn_scan_kernel,
                         cudaFuncAttributeMaxDynamicSharedMemorySize, SCAN_SMEM);

    static cudaStream_t sB = nullptr, sC = nullptr;
    static cudaEvent_t eFork, eC, e1[NSEG], es[NSEG];
    if (sB == nullptr) {
        cudaStreamCreateWithFlags(&sB, cudaStreamNonBlocking);
        cudaStreamCreateWithFlags(&sC, cudaStreamNonBlocking);
        cudaEventCreateWithFlags(&eFork, cudaEventDisableTiming);
        cudaEventCreateWithFlags(&eC,    cudaEventDisableTiming);
        for (int i = 0; i < NSEG; i++) {
            cudaEventCreateWithFlags(&e1[i], cudaEventDisableTiming);
            cudaEventCreateWithFlags(&es[i], cudaEventDisableTiming);
        }
    }

    const int nchunk = SEGT / GR;            // 4 -> grid 256 per segment
    const int grid_seg = BATCH * nchunk;

    // setup + g1s0 (full chip, exposed ~35us)
    transpose_w_kernel<<<NH, NH>>>(W1, W2);
    gemm_tiled_kernel<false><<<grid_seg, 256>>>(input, w1t_ptr, b1, xp_ptr, 0, nchunk);
    cudaEventRecord(eFork, 0);

    // scan seg 0 enqueued before the side-stream GEMMs (claims its SMs first)
    rnn_scan_kernel<<<BATCH, 128, SCAN_SMEM>>>(W1, h_ptr, 0);
    cudaEventRecord(es[0], 0);

    // remaining xp segments on sB (overlap scan0+, on the ~84 free SMs)
    cudaStreamWaitEvent(sB, eFork, 0);
    for (int s = 1; s < NSEG; s++) {
        gemm_tiled_kernel<false><<<grid_seg, 256, 0, sB>>>(input, w1t_ptr, b1, xp_ptr, s * SEGT, nchunk);
        cudaEventRecord(e1[s], sB);
    }

    // scans 1..7, each overlapped by the previous segment's output GEMM on sC
    for (int s = 1; s < NSEG; s++) {
        cudaStreamWaitEvent(0, e1[s], 0);
        rnn_scan_kernel<<<BATCH, 128, SCAN_SMEM>>>(W1, h_ptr, s);
        cudaEventRecord(es[s], 0);

        cudaStreamWaitEvent(sC, es[s - 1], 0);
        gemm_tiled_kernel<true><<<grid_seg, 256, 0, sC>>>(h_ptr, w2t_ptr, b2, out, (s - 1) * SEGT, nchunk);
    }
    cudaEventRecord(eC, sC);

    // final output segment on default stream (after scan7)
    gemm_tiled_kernel<true><<<grid_seg, 256>>>(h_ptr, w2t_ptr, b2, out, (NSEG - 1) * SEGT, nchunk);

    // join
    cudaStreamWaitEvent(0, eC, 0);
}